// round 16
// baseline (speedup 1.0000x reference)
#include <cuda_runtime.h>
#include <cuda_fp16.h>
#include <math.h>
#include <cstdint>
#include <cstring>

#define Bn 2
#define Sn 2048
#define Cn 1024
#define Hn 16
#define Dn 64
#define Mn (Bn*Sn)
#define NT 3072            // fused projection N: [q(1024) | k(1024) | v(1024)]

#define NCTA 296           // 148 SMs x 2 CTAs
#define NGEMM 768          // 24 bn x 32 bm tiles
#define NATTN 512          // 16 qt x 32 bh

// ---------------- scratch (__device__ globals; no allocation) ----------------
__device__ __half g_qh[Bn*Hn*Sn*Dn];          // [B,H,S,D], pre-scaled by 0.125*log2(e)
__device__ __half g_kh[Bn*Hn*Sn*Dn];          // [B,H,S,D]
__device__ __half g_vt[Bn*Hn*Dn*Sn];          // [B,H,D,S]  (pre-transposed V)
__device__ __half g_xh[Mn*Cn];                // x in fp16
__device__ __half g_wt[NT*Cn];                // W^T in fp16: [n][k]

// work-queue / gating state (zero-init; reset by last CTA each launch)
__device__ int g_qgemm, g_qattn, g_done;
__device__ int g_gemm_done[8];

// ---------------- helpers ----------------
__device__ __forceinline__ uint32_t smem_u32(const void* p) {
    uint32_t a;
    asm("{ .reg .u64 t; cvta.to.shared.u64 t, %1; cvt.u32.u64 %0, t; }" : "=r"(a) : "l"(p));
    return a;
}
__device__ __forceinline__ void ldsm4(uint32_t* r, uint32_t addr) {
    asm volatile("ldmatrix.sync.aligned.m8n8.x4.shared.b16 {%0,%1,%2,%3}, [%4];"
        : "=r"(r[0]), "=r"(r[1]), "=r"(r[2]), "=r"(r[3]) : "r"(addr));
}
#define CP_ASYNC16(dst, src) \
    asm volatile("cp.async.cg.shared.global [%0], [%1], 16;" :: "r"(dst), "l"(src))
#define CP_COMMIT()  asm volatile("cp.async.commit_group;" ::: "memory")
#define CP_WAIT(n)   asm volatile("cp.async.wait_group %0;" :: "n"(n) : "memory")

__device__ __forceinline__ void mma_f16(float* c, const uint32_t* a, const uint32_t* b) {
    asm volatile("mma.sync.aligned.m16n8k16.row.col.f32.f16.f16.f32 "
        "{%0,%1,%2,%3}, {%4,%5,%6,%7}, {%8,%9}, {%0,%1,%2,%3};"
        : "+f"(c[0]), "+f"(c[1]), "+f"(c[2]), "+f"(c[3])
        : "r"(a[0]), "r"(a[1]), "r"(a[2]), "r"(a[3]), "r"(b[0]), "r"(b[1]));
}
__device__ __forceinline__ uint32_t packh2(float x, float y) {
    __half2 h = __floats2half2_rn(x, y);
    uint32_t u; memcpy(&u, &h, 4); return u;
}
__device__ __forceinline__ uint32_t h2ex2(uint32_t z) {
    uint32_t p; asm("ex2.approx.f16x2 %0, %1;" : "=r"(p) : "r"(z)); return p;
}

// ---------------------------------------------------------------------------
// Preprocess (separate launch): blocks [0,1024) convert x to fp16 with 4
// independent float4 loads per thread (MLP=4); blocks [1024,4096) transpose
// Wqk/Wv into fp16 Wt [3072][1024].
// ---------------------------------------------------------------------------
#define PREP_XBLK 1024
__global__ __launch_bounds__(256) void prep_kernel(const float* __restrict__ x,
                                                   const float* __restrict__ Wqk,
                                                   const float* __restrict__ Wv) {
    if (blockIdx.x < PREP_XBLK) {
        // 4 independent float4 loads per thread (batched front-loads -> MLP 4)
        float4 v0 = ((const float4*)x)[blockIdx.x * 1024 + 0 * 256 + threadIdx.x];
        float4 v1 = ((const float4*)x)[blockIdx.x * 1024 + 1 * 256 + threadIdx.x];
        float4 v2 = ((const float4*)x)[blockIdx.x * 1024 + 2 * 256 + threadIdx.x];
        float4 v3 = ((const float4*)x)[blockIdx.x * 1024 + 3 * 256 + threadIdx.x];
        __half2* p0 = (__half2*)(g_xh + (size_t)(blockIdx.x * 1024 + 0 * 256 + threadIdx.x) * 4);
        __half2* p1 = (__half2*)(g_xh + (size_t)(blockIdx.x * 1024 + 1 * 256 + threadIdx.x) * 4);
        __half2* p2 = (__half2*)(g_xh + (size_t)(blockIdx.x * 1024 + 2 * 256 + threadIdx.x) * 4);
        __half2* p3 = (__half2*)(g_xh + (size_t)(blockIdx.x * 1024 + 3 * 256 + threadIdx.x) * 4);
        p0[0] = __floats2half2_rn(v0.x, v0.y); p0[1] = __floats2half2_rn(v0.z, v0.w);
        p1[0] = __floats2half2_rn(v1.x, v1.y); p1[1] = __floats2half2_rn(v1.z, v1.w);
        p2[0] = __floats2half2_rn(v2.x, v2.y); p2[1] = __floats2half2_rn(v2.z, v2.w);
        p3[0] = __floats2half2_rn(v3.x, v3.y); p3[1] = __floats2half2_rn(v3.z, v3.w);
        return;
    }
    __shared__ float tbuf[32][33];
    int w  = blockIdx.x - PREP_XBLK;      // 0..3071
    int wx = w % 96, wy = w / 96;         // 96 n-blocks x 32 k-blocks
    const float* W; int N, rowOff, n0;
    if (wx < 64) { W = Wqk; N = 2048; rowOff = 0;    n0 = wx * 32; }
    else         { W = Wv;  N = 1024; rowOff = 2048; n0 = (wx - 64) * 32; }
    int k0 = wy * 32;
    int tx = threadIdx.x & 31, ty = threadIdx.x >> 5;   // 32 x 8
    #pragma unroll
    for (int j = 0; j < 4; j++)
        tbuf[ty + 8*j][tx] = W[(size_t)(k0 + ty + 8*j) * N + n0 + tx];
    __syncthreads();
    #pragma unroll
    for (int j = 0; j < 4; j++) {
        int n = n0 + ty + 8*j, k = k0 + tx;
        g_wt[(size_t)(rowOff + n) * Cn + k] = __float2half_rn(tbuf[tx][ty + 8*j]);
    }
}

// ---------------------------------------------------------------------------
// GEMM tile (R8 config): CTA tile 128x128, warp tile 64x32, K-chunk 64,
// 3-stage cp.async pipeline, ldmatrix fragment loads, fp16 HMMA fp32 accum.
// ---------------------------------------------------------------------------
#define KCH 64
#define RSTR 144
#define TILE_B (128 * RSTR)             // 18432 B
#define BUF_B  (2 * TILE_B)             // 36864 B per stage
#define NSTAGE 3
#define FUSED_SMEM (NSTAGE * BUF_B)     // 110592 B

__device__ void gemm_tile(int bn, int bm, const float* __restrict__ bqk,
                          const float* __restrict__ bv, char* smem) {
    const uint32_t sb = smem_u32(smem);
    const int tid  = threadIdx.x;
    const int warp = tid >> 5;
    const int lane = tid & 31;
    const int g    = lane >> 2;
    const int t    = lane & 3;
    const int wm = (warp >> 2) * 64;
    const int wn = (warp & 3) * 32;

    float c[4][4][4];
    #pragma unroll
    for (int i = 0; i < 4; i++)
        #pragma unroll
        for (int j = 0; j < 4; j++)
            #pragma unroll
            for (int r = 0; r < 4; r++) c[i][j][r] = 0.f;

    const uint32_t arow = (uint32_t)(wm + (lane & 7) + (lane & 8));
    const uint32_t aoff = arow * RSTR + ((lane & 16) ? 16u : 0u);
    const uint32_t brow = (uint32_t)(wn + (lane & 7) + ((lane & 16) ? 8 : 0));
    const uint32_t boff = brow * RSTR + ((lane & 8) ? 16u : 0u);

    auto issue_chunk = [&](int kc, int stage) {
        const uint32_t base = sb + stage * BUF_B;
        #pragma unroll
        for (int i = 0; i < 4; i++) {
            int idx = tid + i * 256;
            int row = idx >> 3;
            int seg = idx & 7;
            uint32_t so = (uint32_t)(row * RSTR + seg * 16);
            size_t goA = (size_t)(bm + row) * Cn + kc * KCH + seg * 8;
            size_t goB = (size_t)(bn + row) * Cn + kc * KCH + seg * 8;
            CP_ASYNC16(base + so,          g_xh + goA);
            CP_ASYNC16(base + TILE_B + so, g_wt + goB);
        }
        CP_COMMIT();
    };

    issue_chunk(0, 0);
    issue_chunk(1, 1);

    const int NCH = Cn / KCH;             // 16
    int stage = 0;
    int nstage = 2;
    for (int kc = 0; kc < NCH; kc++) {
        if (kc < NCH - 2) { CP_WAIT(1); } else { CP_WAIT(0); }
        __syncthreads();
        if (kc + 2 < NCH) issue_chunk(kc + 2, nstage);

        const uint32_t Ab = sb + stage * BUF_B + aoff;
        const uint32_t Bb = sb + stage * BUF_B + TILE_B + boff;

        #pragma unroll
        for (int ks = 0; ks < 4; ks++) {
            const uint32_t ko = ks * 32;
            uint32_t a[4][4], b[2][4];
            #pragma unroll
            for (int p = 0; p < 2; p++)
                ldsm4(b[p], Bb + p * 16 * RSTR + ko);
            #pragma unroll
            for (int mt = 0; mt < 4; mt++)
                ldsm4(a[mt], Ab + mt * 16 * RSTR + ko);
            #pragma unroll
            for (int mt = 0; mt < 4; mt++)
                #pragma unroll
                for (int nt = 0; nt < 4; nt++)
                    mma_f16(c[mt][nt], a[mt], &b[nt >> 1][(nt & 1) * 2]);
        }
        stage = (stage == NSTAGE - 1) ? 0 : stage + 1;
        nstage = (nstage == NSTAGE - 1) ? 0 : nstage + 1;
        __syncthreads();
    }

    // Epilogue: bias add; q scaled by 0.125*log2e; v transposed to [B,H,D,S].
    const bool isV = (bn >= 2048);
    const bool isQ = (bn < 1024);
    const float scl = isQ ? 0.18033688f : 1.0f;
    const float* bias = isV ? (bv + (bn - 2048)) : (bqk + bn);
    const int nb = isV ? (bn - 2048) : (bn & 1023);
    __half* qkdst = isQ ? g_qh : g_kh;

    #pragma unroll
    for (int mt = 0; mt < 4; mt++) {
        int m0 = bm + wm + mt * 16 + g;
        int bb0 = m0 >> 11, s0 = m0 & 2047;
        int m1 = m0 + 8;
        int bb1 = m1 >> 11, s1 = m1 & 2047;
        #pragma unroll
        for (int nt = 0; nt < 4; nt++) {
            int nf = wn + nt * 8 + 2 * t;
            int nloc = nb + nf;
            float b0 = bias[nf];
            float b1 = bias[nf + 1];
            int h = nloc >> 6, d = nloc & 63;
            float v00 = (c[mt][nt][0] + b0) * scl, v01 = (c[mt][nt][1] + b1) * scl;
            float v10 = (c[mt][nt][2] + b0) * scl, v11 = (c[mt][nt][3] + b1) * scl;
            if (!isV) {
                __half2* p0 = (__half2*)(qkdst + (((size_t)bb0 * Hn + h) * Sn + s0) * Dn + d);
                __half2* p1 = (__half2*)(qkdst + (((size_t)bb1 * Hn + h) * Sn + s1) * Dn + d);
                *p0 = __floats2half2_rn(v00, v01);
                *p1 = __floats2half2_rn(v10, v11);
            } else {
                size_t base0 = (((size_t)bb0 * Hn + h) * Dn + d) * Sn;
                size_t base1 = (((size_t)bb1 * Hn + h) * Dn + d) * Sn;
                g_vt[base0 + s0]      = __float2half_rn(v00);
                g_vt[base0 + Sn + s0] = __float2half_rn(v01);
                g_vt[base1 + s1]      = __float2half_rn(v10);
                g_vt[base1 + Sn + s1] = __float2half_rn(v11);
            }
        }
    }
}

// ---------------------------------------------------------------------------
// Attention item (R13 logic): 128 q rows x (b,h), shift-free softmax, f16x2
// exp2, row sums via ones-MMA, off-diag fast path + diagonal mask path.
// ---------------------------------------------------------------------------
#define AKSTR 144
#define AVSTR 272
#define OFF_Q   0
#define OFF_K0  18432
#define OFF_K1  36864
#define OFF_VT0 55296
#define OFF_VT1 72704

__device__ void attn_item(int qt, int b, int h, float* __restrict__ out, char* smem) {
    const uint32_t sb = smem_u32(smem);
    const int tid = threadIdx.x, warp = tid >> 5, lane = tid & 31;
    const int g = lane >> 2, t = lane & 3;
    const int bh = b * 16 + h;

    const __half* qg  = g_qh + ((size_t)bh * Sn + (size_t)qt * 128) * Dn;
    const __half* kg  = g_kh + (size_t)bh * Sn * Dn;
    const __half* vtg = g_vt + (size_t)bh * Dn * Sn;

    #pragma unroll
    for (int i = 0; i < 4; i++) {
        int idx = tid + i * 256, row = idx >> 3, ch = idx & 7;
        CP_ASYNC16(sb + OFF_Q + row * AKSTR + ch * 16, qg + row * 64 + ch * 8);
    }
    CP_COMMIT();

    auto cp_tiles = [&](int kt2, int buf2) {
        const __half* ksrc = kg + (size_t)kt2 * 128 * 64;
        uint32_t kdst = sb + (buf2 ? OFF_K1 : OFF_K0);
        #pragma unroll
        for (int i = 0; i < 4; i++) {
            int idx = tid + i * 256, row = idx >> 3, ch = idx & 7;
            CP_ASYNC16(kdst + row * AKSTR + ch * 16, ksrc + row * 64 + ch * 8);
        }
        const __half* vsrc = vtg + (size_t)kt2 * 128;
        uint32_t vdst = sb + (buf2 ? OFF_VT1 : OFF_VT0);
        #pragma unroll
        for (int i = 0; i < 4; i++) {
            int idx = tid + i * 256, row = idx >> 4, ch = idx & 15;
            CP_ASYNC16(vdst + row * AVSTR + ch * 16, vsrc + (size_t)row * Sn + ch * 8);
        }
        CP_COMMIT();
    };

    cp_tiles(0, 0);
    CP_WAIT(0);
    __syncthreads();

    const uint32_t arow = (uint32_t)((lane & 7) + (lane & 8));
    const uint32_t abyte = (lane & 16) ? 16u : 0u;
    const uint32_t krow = (uint32_t)((lane & 7) + ((lane & 16) ? 8 : 0));
    const uint32_t kbyte = (lane & 8) ? 16u : 0u;

    uint32_t qa[4][4];
    #pragma unroll
    for (int ks = 0; ks < 4; ks++)
        ldsm4(qa[ks], sb + OFF_Q + (16 * warp + arow) * AKSTR + ks * 32 + abyte);

    float co[8][4];
    float cl[4];
    #pragma unroll
    for (int nf = 0; nf < 8; nf++)
        #pragma unroll
        for (int j = 0; j < 4; j++) co[nf][j] = 0.f;
    #pragma unroll
    for (int j = 0; j < 4; j++) cl[j] = 0.f;

    const uint32_t ones2[2] = {0x3C003C00u, 0x3C003C00u};
    const int row0g = qt * 128 + 16 * warp + g;
    const int rmaxg = qt * 128 + 16 * warp + 15;

    // off-diagonal tiles: mask-free fast path
    for (int kt = 0; kt < qt; kt++) {
        const int buf = kt & 1;
        if (kt > 0) {
            CP_WAIT(0);
            __syncthreads();
        }
        cp_tiles(kt + 1, buf ^ 1);

        const uint32_t Kb = sb + (buf ? OFF_K1 : OFF_K0);
        const uint32_t Vb = sb + (buf ? OFF_VT1 : OFF_VT0);

        #pragma unroll
        for (int hf = 0; hf < 2; hf++) {
            float sc[8][4];
            #pragma unroll
            for (int nf = 0; nf < 8; nf++)
                #pragma unroll
                for (int j = 0; j < 4; j++) sc[nf][j] = 0.f;

            #pragma unroll
            for (int ks = 0; ks < 4; ks++) {
                uint32_t kb[4][4];
                #pragma unroll
                for (int p = 0; p < 4; p++)
                    ldsm4(kb[p], Kb + (64 * hf + 16 * p + krow) * AKSTR + ks * 32 + kbyte);
                #pragma unroll
                for (int p = 0; p < 4; p++) {
                    mma_f16(sc[2 * p],     qa[ks], &kb[p][0]);
                    mma_f16(sc[2 * p + 1], qa[ks], &kb[p][2]);
                }
            }

            #pragma unroll
            for (int kk = 0; kk < 4; kk++) {
                uint32_t pa[4];
                pa[0] = h2ex2(packh2(sc[2*kk][0],     sc[2*kk][1]));
                pa[1] = h2ex2(packh2(sc[2*kk][2],     sc[2*kk][3]));
                pa[2] = h2ex2(packh2(sc[2*kk + 1][0], sc[2*kk + 1][1]));
                pa[3] = h2ex2(packh2(sc[2*kk + 1][2], sc[2*kk + 1][3]));
                mma_f16(cl, pa, ones2);
                #pragma unroll
                for (int p = 0; p < 4; p++) {
                    uint32_t vb[4];
                    ldsm4(vb, Vb + (16 * p + krow) * AVSTR + 128 * hf + 32 * kk + kbyte);
                    mma_f16(co[2 * p],     pa, &vb[0]);
                    mma_f16(co[2 * p + 1], pa, &vb[2]);
                }
            }
        }
    }

    // diagonal tile: causal mask + fully-masked-group skip
    {
        const int kt = qt;
        const int buf = kt & 1;
        if (kt > 0) {
            CP_WAIT(0);
            __syncthreads();
        }
        const uint32_t Kb = sb + (buf ? OFF_K1 : OFF_K0);
        const uint32_t Vb = sb + (buf ? OFF_VT1 : OFF_VT0);

        #pragma unroll
        for (int hf = 0; hf < 2; hf++) {
            bool keep[4];
            #pragma unroll
            for (int p = 0; p < 4; p++)
                keep[p] = (kt * 128 + 64 * hf + 16 * p) <= rmaxg;
            if (!keep[0]) continue;

            float sc[8][4];
            #pragma unroll
            for (int nf = 0; nf < 8; nf++)
                #pragma unroll
                for (int j = 0; j < 4; j++) sc[nf][j] = 0.f;

            #pragma unroll
            for (int ks = 0; ks < 4; ks++) {
                uint32_t kb[4][4];
                #pragma unroll
                for (int p = 0; p < 4; p++)
                    if (keep[p])
                        ldsm4(kb[p], Kb + (64 * hf + 16 * p + krow) * AKSTR + ks * 32 + kbyte);
                #pragma unroll
                for (int p = 0; p < 4; p++) {
                    if (!keep[p]) continue;
                    mma_f16(sc[2 * p],     qa[ks], &kb[p][0]);
                    mma_f16(sc[2 * p + 1], qa[ks], &kb[p][2]);
                }
            }

            #pragma unroll
            for (int nf = 0; nf < 8; nf++) {
                int c0 = kt * 128 + 64 * hf + 8 * nf + 2 * t;
                if (c0     > row0g)     sc[nf][0] = -1e30f;
                if (c0 + 1 > row0g)     sc[nf][1] = -1e30f;
                if (c0     > row0g + 8) sc[nf][2] = -1e30f;
                if (c0 + 1 > row0g + 8) sc[nf][3] = -1e30f;
            }

            #pragma unroll
            for (int kk = 0; kk < 4; kk++) {
                if (!keep[kk]) continue;
                uint32_t pa[4];
                pa[0] = h2ex2(packh2(sc[2*kk][0],     sc[2*kk][1]));
                pa[1] = h2ex2(packh2(sc[2*kk][2],     sc[2*kk][3]));
                pa[2] = h2ex2(packh2(sc[2*kk + 1][0], sc[2*kk + 1][1]));
                pa[3] = h2ex2(packh2(sc[2*kk + 1][2], sc[2*kk + 1][3]));
                mma_f16(cl, pa, ones2);
                #pragma unroll
                for (int p = 0; p < 4; p++) {
                    uint32_t vb[4];
                    ldsm4(vb, Vb + (16 * p + krow) * AVSTR + 128 * hf + 32 * kk + kbyte);
                    mma_f16(co[2 * p],     pa, &vb[0]);
                    mma_f16(co[2 * p + 1], pa, &vb[2]);
                }
            }
        }
    }

    float inv0 = 1.f / cl[0], inv1 = 1.f / cl[2];
    float* op0 = out + ((size_t)b * Sn + row0g) * Cn + h * 64;
    float* op1 = op0 + 8 * Cn;
    #pragma unroll
    for (int nf = 0; nf < 8; nf++) {
        int d = 8 * nf + 2 * t;
        *(float2*)(op0 + d) = make_float2(co[nf][0] * inv0, co[nf][1] * inv0);
        *(float2*)(op1 + d) = make_float2(co[nf][2] * inv1, co[nf][3] * inv1);
    }
}

// ---------------------------------------------------------------------------
// Persistent fused kernel: gemm (head-pair-major, flags) then attention.
// Attention order: first 128 items hp-major (hp 0,1 — overlap GEMM tail),
// remaining 384 items LPT (qt descending across hp 2..7) to balance the tail.
// ---------------------------------------------------------------------------
__global__ __launch_bounds__(256, 2) void gemm_attn_kernel(const float* __restrict__ bqk,
                                                           const float* __restrict__ bv,
                                                           float* __restrict__ out) {
    extern __shared__ __align__(128) char smem[];
    __shared__ int s_item;
    const int tid = threadIdx.x;

    // ---- phase 1: GEMM (head-pair-major item order) ----
    for (;;) {
        if (tid == 0) s_item = atomicAdd(&g_qgemm, 1);
        __syncthreads();
        int it = s_item;
        __syncthreads();
        if (it >= NGEMM) break;
        int grp = it / 96;                    // head-pair group 0..7
        int w   = it % 96;
        int bn_idx = grp + 8 * (w % 3);       // {grp, grp+8, grp+16}
        int bm_idx = w / 3;                   // 0..31
        gemm_tile(bn_idx * 128, bm_idx * 128, bqk, bv, smem);
        __threadfence();
        __syncthreads();
        if (tid == 0) atomicAdd(&g_gemm_done[grp], 1);
    }

    // ---- phase 2: attention ----
    for (;;) {
        if (tid == 0) s_item = atomicAdd(&g_qattn, 1);
        __syncthreads();
        int j = s_item;
        __syncthreads();
        if (j >= NATTN) break;
        int hp, qt, sub;
        if (j < 128) {
            // hp-major for hp 0,1: qt descending within hp
            hp  = j >> 6;
            int r = j & 63;
            qt  = 15 - (r >> 2);
            sub = r & 3;
        } else {
            // LPT: qt descending across hp 2..7
            int idx = j - 128;                // 0..383
            qt  = 15 - idx / 24;
            int r = idx % 24;
            hp  = 2 + (r >> 2);
            sub = r & 3;
        }
        int h = 2 * hp + (sub & 1);
        int b = sub >> 1;
        if (tid == 0) {
            while (atomicAdd(&g_gemm_done[hp], 0) < 96) __nanosleep(128);
        }
        __syncthreads();
        __threadfence();
        attn_item(qt, b, h, out, smem);
    }

    // ---- finish: last CTA resets all counters for the next graph replay ----
    __syncthreads();
    if (tid == 0) {
        int d = atomicAdd(&g_done, 1);
        if (d == NCTA - 1) {
            g_qgemm = 0; g_qattn = 0; g_done = 0;
            #pragma unroll
            for (int i = 0; i < 8; i++) g_gemm_done[i] = 0;
            __threadfence();
        }
    }
}

// ---------------------------------------------------------------------------
extern "C" void kernel_launch(void* const* d_in, const int* in_sizes, int n_in,
                              void* d_out, int out_size) {
    const float* x   = (const float*)d_in[0];
    const float* Wqk = (const float*)d_in[1];
    const float* bqk = (const float*)d_in[2];
    const float* Wv  = (const float*)d_in[3];
    const float* bv  = (const float*)d_in[4];
    float* out = (float*)d_out;

    prep_kernel<<<PREP_XBLK + 3072, 256>>>(x, Wqk, Wv);

    cudaFuncSetAttribute(gemm_attn_kernel, cudaFuncAttributeMaxDynamicSharedMemorySize, FUSED_SMEM);
    gemm_attn_kernel<<<NCTA, 256, FUSED_SMEM>>>(bqk, bv, out);
}

// round 17
// speedup vs baseline: 1.0172x; 1.0172x over previous
#include <cuda_runtime.h>
#include <cuda_fp16.h>
#include <math.h>
#include <cstdint>
#include <cstring>

#define Bn 2
#define Sn 2048
#define Cn 1024
#define Hn 16
#define Dn 64
#define Mn (Bn*Sn)
#define NT 3072            // fused projection N: [q(1024) | k(1024) | v(1024)]

#define NCTA 296           // 148 SMs x 2 CTAs
#define NGEMM 768          // 24 bn x 32 bm tiles
#define NATTN 512          // 16 qt x 32 bh

// ---------------- scratch (__device__ globals; no allocation) ----------------
__device__ __half g_qh[Bn*Hn*Sn*Dn];          // [B,H,S,D], pre-scaled by 0.125*log2(e)
__device__ __half g_kh[Bn*Hn*Sn*Dn];          // [B,H,S,D]
__device__ __half g_vt[Bn*Hn*Dn*Sn];          // [B,H,D,S]  (pre-transposed V)
__device__ __half g_xh[Mn*Cn];                // x in fp16
__device__ __half g_wt[NT*Cn];                // W^T in fp16: [n][k]

// work-queue / gating state (zero-init; reset by last CTA each launch)
__device__ int g_qgemm, g_qattn, g_done;
__device__ int g_gemm_done[8];

// ---------------- helpers ----------------
__device__ __forceinline__ uint32_t smem_u32(const void* p) {
    uint32_t a;
    asm("{ .reg .u64 t; cvta.to.shared.u64 t, %1; cvt.u32.u64 %0, t; }" : "=r"(a) : "l"(p));
    return a;
}
__device__ __forceinline__ void ldsm4(uint32_t* r, uint32_t addr) {
    asm volatile("ldmatrix.sync.aligned.m8n8.x4.shared.b16 {%0,%1,%2,%3}, [%4];"
        : "=r"(r[0]), "=r"(r[1]), "=r"(r[2]), "=r"(r[3]) : "r"(addr));
}
#define CP_ASYNC16(dst, src) \
    asm volatile("cp.async.cg.shared.global [%0], [%1], 16;" :: "r"(dst), "l"(src))
#define CP_COMMIT()  asm volatile("cp.async.commit_group;" ::: "memory")
#define CP_WAIT(n)   asm volatile("cp.async.wait_group %0;" :: "n"(n) : "memory")

__device__ __forceinline__ void mma_f16(float* c, const uint32_t* a, const uint32_t* b) {
    asm volatile("mma.sync.aligned.m16n8k16.row.col.f32.f16.f16.f32 "
        "{%0,%1,%2,%3}, {%4,%5,%6,%7}, {%8,%9}, {%0,%1,%2,%3};"
        : "+f"(c[0]), "+f"(c[1]), "+f"(c[2]), "+f"(c[3])
        : "r"(a[0]), "r"(a[1]), "r"(a[2]), "r"(a[3]), "r"(b[0]), "r"(b[1]));
}
__device__ __forceinline__ uint32_t packh2(float x, float y) {
    __half2 h = __floats2half2_rn(x, y);
    uint32_t u; memcpy(&u, &h, 4); return u;
}
__device__ __forceinline__ uint32_t h2ex2(uint32_t z) {
    uint32_t p; asm("ex2.approx.f16x2 %0, %1;" : "=r"(p) : "r"(z)); return p;
}
__device__ __forceinline__ __half2 u2h2(uint32_t u) {
    __half2 h; memcpy(&h, &u, 4); return h;
}

// ---------------------------------------------------------------------------
// Preprocess (separate launch): blocks [0,1024) convert x to fp16 with 4
// independent float4 loads per thread (MLP=4); blocks [1024,4096) transpose
// Wqk/Wv into fp16 Wt [3072][1024].
// ---------------------------------------------------------------------------
#define PREP_XBLK 1024
__global__ __launch_bounds__(256) void prep_kernel(const float* __restrict__ x,
                                                   const float* __restrict__ Wqk,
                                                   const float* __restrict__ Wv) {
    if (blockIdx.x < PREP_XBLK) {
        float4 v0 = ((const float4*)x)[blockIdx.x * 1024 + 0 * 256 + threadIdx.x];
        float4 v1 = ((const float4*)x)[blockIdx.x * 1024 + 1 * 256 + threadIdx.x];
        float4 v2 = ((const float4*)x)[blockIdx.x * 1024 + 2 * 256 + threadIdx.x];
        float4 v3 = ((const float4*)x)[blockIdx.x * 1024 + 3 * 256 + threadIdx.x];
        __half2* p0 = (__half2*)(g_xh + (size_t)(blockIdx.x * 1024 + 0 * 256 + threadIdx.x) * 4);
        __half2* p1 = (__half2*)(g_xh + (size_t)(blockIdx.x * 1024 + 1 * 256 + threadIdx.x) * 4);
        __half2* p2 = (__half2*)(g_xh + (size_t)(blockIdx.x * 1024 + 2 * 256 + threadIdx.x) * 4);
        __half2* p3 = (__half2*)(g_xh + (size_t)(blockIdx.x * 1024 + 3 * 256 + threadIdx.x) * 4);
        p0[0] = __floats2half2_rn(v0.x, v0.y); p0[1] = __floats2half2_rn(v0.z, v0.w);
        p1[0] = __floats2half2_rn(v1.x, v1.y); p1[1] = __floats2half2_rn(v1.z, v1.w);
        p2[0] = __floats2half2_rn(v2.x, v2.y); p2[1] = __floats2half2_rn(v2.z, v2.w);
        p3[0] = __floats2half2_rn(v3.x, v3.y); p3[1] = __floats2half2_rn(v3.z, v3.w);
        return;
    }
    __shared__ float tbuf[32][33];
    int w  = blockIdx.x - PREP_XBLK;      // 0..3071
    int wx = w % 96, wy = w / 96;         // 96 n-blocks x 32 k-blocks
    const float* W; int N, rowOff, n0;
    if (wx < 64) { W = Wqk; N = 2048; rowOff = 0;    n0 = wx * 32; }
    else         { W = Wv;  N = 1024; rowOff = 2048; n0 = (wx - 64) * 32; }
    int k0 = wy * 32;
    int tx = threadIdx.x & 31, ty = threadIdx.x >> 5;   // 32 x 8
    #pragma unroll
    for (int j = 0; j < 4; j++)
        tbuf[ty + 8*j][tx] = W[(size_t)(k0 + ty + 8*j) * N + n0 + tx];
    __syncthreads();
    #pragma unroll
    for (int j = 0; j < 4; j++) {
        int n = n0 + ty + 8*j, k = k0 + tx;
        g_wt[(size_t)(rowOff + n) * Cn + k] = __float2half_rn(tbuf[tx][ty + 8*j]);
    }
}

// ---------------------------------------------------------------------------
// GEMM tile (R8 config): CTA tile 128x128, warp tile 64x32, K-chunk 64,
// 3-stage cp.async pipeline, ldmatrix fragment loads, fp16 HMMA fp32 accum.
// ---------------------------------------------------------------------------
#define KCH 64
#define RSTR 144
#define TILE_B (128 * RSTR)             // 18432 B
#define BUF_B  (2 * TILE_B)             // 36864 B per stage
#define NSTAGE 3
#define FUSED_SMEM (NSTAGE * BUF_B)     // 110592 B

__device__ void gemm_tile(int bn, int bm, const float* __restrict__ bqk,
                          const float* __restrict__ bv, char* smem) {
    const uint32_t sb = smem_u32(smem);
    const int tid  = threadIdx.x;
    const int warp = tid >> 5;
    const int lane = tid & 31;
    const int g    = lane >> 2;
    const int t    = lane & 3;
    const int wm = (warp >> 2) * 64;
    const int wn = (warp & 3) * 32;

    float c[4][4][4];
    #pragma unroll
    for (int i = 0; i < 4; i++)
        #pragma unroll
        for (int j = 0; j < 4; j++)
            #pragma unroll
            for (int r = 0; r < 4; r++) c[i][j][r] = 0.f;

    const uint32_t arow = (uint32_t)(wm + (lane & 7) + (lane & 8));
    const uint32_t aoff = arow * RSTR + ((lane & 16) ? 16u : 0u);
    const uint32_t brow = (uint32_t)(wn + (lane & 7) + ((lane & 16) ? 8 : 0));
    const uint32_t boff = brow * RSTR + ((lane & 8) ? 16u : 0u);

    auto issue_chunk = [&](int kc, int stage) {
        const uint32_t base = sb + stage * BUF_B;
        #pragma unroll
        for (int i = 0; i < 4; i++) {
            int idx = tid + i * 256;
            int row = idx >> 3;
            int seg = idx & 7;
            uint32_t so = (uint32_t)(row * RSTR + seg * 16);
            size_t goA = (size_t)(bm + row) * Cn + kc * KCH + seg * 8;
            size_t goB = (size_t)(bn + row) * Cn + kc * KCH + seg * 8;
            CP_ASYNC16(base + so,          g_xh + goA);
            CP_ASYNC16(base + TILE_B + so, g_wt + goB);
        }
        CP_COMMIT();
    };

    issue_chunk(0, 0);
    issue_chunk(1, 1);

    const int NCH = Cn / KCH;             // 16
    int stage = 0;
    int nstage = 2;
    for (int kc = 0; kc < NCH; kc++) {
        if (kc < NCH - 2) { CP_WAIT(1); } else { CP_WAIT(0); }
        __syncthreads();
        if (kc + 2 < NCH) issue_chunk(kc + 2, nstage);

        const uint32_t Ab = sb + stage * BUF_B + aoff;
        const uint32_t Bb = sb + stage * BUF_B + TILE_B + boff;

        #pragma unroll
        for (int ks = 0; ks < 4; ks++) {
            const uint32_t ko = ks * 32;
            uint32_t a[4][4], b[2][4];
            #pragma unroll
            for (int p = 0; p < 2; p++)
                ldsm4(b[p], Bb + p * 16 * RSTR + ko);
            #pragma unroll
            for (int mt = 0; mt < 4; mt++)
                ldsm4(a[mt], Ab + mt * 16 * RSTR + ko);
            #pragma unroll
            for (int mt = 0; mt < 4; mt++)
                #pragma unroll
                for (int nt = 0; nt < 4; nt++)
                    mma_f16(c[mt][nt], a[mt], &b[nt >> 1][(nt & 1) * 2]);
        }
        stage = (stage == NSTAGE - 1) ? 0 : stage + 1;
        nstage = (nstage == NSTAGE - 1) ? 0 : nstage + 1;
        __syncthreads();
    }

    // Epilogue: bias add; q scaled by 0.125*log2e; v transposed to [B,H,D,S].
    const bool isV = (bn >= 2048);
    const bool isQ = (bn < 1024);
    const float scl = isQ ? 0.18033688f : 1.0f;
    const float* bias = isV ? (bv + (bn - 2048)) : (bqk + bn);
    const int nb = isV ? (bn - 2048) : (bn & 1023);
    __half* qkdst = isQ ? g_qh : g_kh;

    #pragma unroll
    for (int mt = 0; mt < 4; mt++) {
        int m0 = bm + wm + mt * 16 + g;
        int bb0 = m0 >> 11, s0 = m0 & 2047;
        int m1 = m0 + 8;
        int bb1 = m1 >> 11, s1 = m1 & 2047;
        #pragma unroll
        for (int nt = 0; nt < 4; nt++) {
            int nf = wn + nt * 8 + 2 * t;
            int nloc = nb + nf;
            float b0 = bias[nf];
            float b1 = bias[nf + 1];
            int h = nloc >> 6, d = nloc & 63;
            float v00 = (c[mt][nt][0] + b0) * scl, v01 = (c[mt][nt][1] + b1) * scl;
            float v10 = (c[mt][nt][2] + b0) * scl, v11 = (c[mt][nt][3] + b1) * scl;
            if (!isV) {
                __half2* p0 = (__half2*)(qkdst + (((size_t)bb0 * Hn + h) * Sn + s0) * Dn + d);
                __half2* p1 = (__half2*)(qkdst + (((size_t)bb1 * Hn + h) * Sn + s1) * Dn + d);
                *p0 = __floats2half2_rn(v00, v01);
                *p1 = __floats2half2_rn(v10, v11);
            } else {
                size_t base0 = (((size_t)bb0 * Hn + h) * Dn + d) * Sn;
                size_t base1 = (((size_t)bb1 * Hn + h) * Dn + d) * Sn;
                g_vt[base0 + s0]      = __float2half_rn(v00);
                g_vt[base0 + Sn + s0] = __float2half_rn(v01);
                g_vt[base1 + s1]      = __float2half_rn(v10);
                g_vt[base1 + Sn + s1] = __float2half_rn(v11);
            }
        }
    }
}

// ---------------------------------------------------------------------------
// Attention item: 128 q rows x (b,h), shift-free softmax, f16x2 exp2.
// R17: row sums extracted from the packed f16 P registers via __hadd2 +
// f16x2->f32 convert on the FMA/ALU pipes (the ones-operand l-MMA is gone:
// -8 tensor MMAs per tile-warp). Cross-lane reduce once at the epilogue.
// ---------------------------------------------------------------------------
#define AKSTR 144
#define AVSTR 272
#define OFF_Q   0
#define OFF_K0  18432
#define OFF_K1  36864
#define OFF_VT0 55296
#define OFF_VT1 72704

__device__ void attn_item(int qt, int b, int h, float* __restrict__ out, char* smem) {
    const uint32_t sb = smem_u32(smem);
    const int tid = threadIdx.x, warp = tid >> 5, lane = tid & 31;
    const int g = lane >> 2, t = lane & 3;
    const int bh = b * 16 + h;

    const __half* qg  = g_qh + ((size_t)bh * Sn + (size_t)qt * 128) * Dn;
    const __half* kg  = g_kh + (size_t)bh * Sn * Dn;
    const __half* vtg = g_vt + (size_t)bh * Dn * Sn;

    #pragma unroll
    for (int i = 0; i < 4; i++) {
        int idx = tid + i * 256, row = idx >> 3, ch = idx & 7;
        CP_ASYNC16(sb + OFF_Q + row * AKSTR + ch * 16, qg + row * 64 + ch * 8);
    }
    CP_COMMIT();

    auto cp_tiles = [&](int kt2, int buf2) {
        const __half* ksrc = kg + (size_t)kt2 * 128 * 64;
        uint32_t kdst = sb + (buf2 ? OFF_K1 : OFF_K0);
        #pragma unroll
        for (int i = 0; i < 4; i++) {
            int idx = tid + i * 256, row = idx >> 3, ch = idx & 7;
            CP_ASYNC16(kdst + row * AKSTR + ch * 16, ksrc + row * 64 + ch * 8);
        }
        const __half* vsrc = vtg + (size_t)kt2 * 128;
        uint32_t vdst = sb + (buf2 ? OFF_VT1 : OFF_VT0);
        #pragma unroll
        for (int i = 0; i < 4; i++) {
            int idx = tid + i * 256, row = idx >> 4, ch = idx & 15;
            CP_ASYNC16(vdst + row * AVSTR + ch * 16, vsrc + (size_t)row * Sn + ch * 8);
        }
        CP_COMMIT();
    };

    cp_tiles(0, 0);
    CP_WAIT(0);
    __syncthreads();

    const uint32_t arow = (uint32_t)((lane & 7) + (lane & 8));
    const uint32_t abyte = (lane & 16) ? 16u : 0u;
    const uint32_t krow = (uint32_t)((lane & 7) + ((lane & 16) ? 8 : 0));
    const uint32_t kbyte = (lane & 8) ? 16u : 0u;

    uint32_t qa[4][4];
    #pragma unroll
    for (int ks = 0; ks < 4; ks++)
        ldsm4(qa[ks], sb + OFF_Q + (16 * warp + arow) * AKSTR + ks * 32 + abyte);

    float co[8][4];
    float l0 = 0.f, l1 = 0.f;     // per-lane partial row sums (cols 2t, 2t+1 of each frag)
    #pragma unroll
    for (int nf = 0; nf < 8; nf++)
        #pragma unroll
        for (int j = 0; j < 4; j++) co[nf][j] = 0.f;

    const int row0g = qt * 128 + 16 * warp + g;
    const int rmaxg = qt * 128 + 16 * warp + 15;

    // off-diagonal tiles: mask-free fast path
    for (int kt = 0; kt < qt; kt++) {
        const int buf = kt & 1;
        if (kt > 0) {
            CP_WAIT(0);
            __syncthreads();
        }
        cp_tiles(kt + 1, buf ^ 1);

        const uint32_t Kb = sb + (buf ? OFF_K1 : OFF_K0);
        const uint32_t Vb = sb + (buf ? OFF_VT1 : OFF_VT0);

        #pragma unroll
        for (int hf = 0; hf < 2; hf++) {
            float sc[8][4];
            #pragma unroll
            for (int nf = 0; nf < 8; nf++)
                #pragma unroll
                for (int j = 0; j < 4; j++) sc[nf][j] = 0.f;

            #pragma unroll
            for (int ks = 0; ks < 4; ks++) {
                uint32_t kb[4][4];
                #pragma unroll
                for (int p = 0; p < 4; p++)
                    ldsm4(kb[p], Kb + (64 * hf + 16 * p + krow) * AKSTR + ks * 32 + kbyte);
                #pragma unroll
                for (int p = 0; p < 4; p++) {
                    mma_f16(sc[2 * p],     qa[ks], &kb[p][0]);
                    mma_f16(sc[2 * p + 1], qa[ks], &kb[p][2]);
                }
            }

            #pragma unroll
            for (int kk = 0; kk < 4; kk++) {
                uint32_t pa[4];
                pa[0] = h2ex2(packh2(sc[2*kk][0],     sc[2*kk][1]));
                pa[1] = h2ex2(packh2(sc[2*kk][2],     sc[2*kk][3]));
                pa[2] = h2ex2(packh2(sc[2*kk + 1][0], sc[2*kk + 1][1]));
                pa[3] = h2ex2(packh2(sc[2*kk + 1][2], sc[2*kk + 1][3]));
                // row sums from packed P (FMA/ALU pipes, not tensor)
                {
                    float2 f0 = __half22float2(__hadd2(u2h2(pa[0]), u2h2(pa[2])));
                    float2 f1 = __half22float2(__hadd2(u2h2(pa[1]), u2h2(pa[3])));
                    l0 += f0.x + f0.y;
                    l1 += f1.x + f1.y;
                }
                #pragma unroll
                for (int p = 0; p < 4; p++) {
                    uint32_t vb[4];
                    ldsm4(vb, Vb + (16 * p + krow) * AVSTR + 128 * hf + 32 * kk + kbyte);
                    mma_f16(co[2 * p],     pa, &vb[0]);
                    mma_f16(co[2 * p + 1], pa, &vb[2]);
                }
            }
        }
    }

    // diagonal tile: causal mask + fully-masked-group skip
    {
        const int kt = qt;
        const int buf = kt & 1;
        if (kt > 0) {
            CP_WAIT(0);
            __syncthreads();
        }
        const uint32_t Kb = sb + (buf ? OFF_K1 : OFF_K0);
        const uint32_t Vb = sb + (buf ? OFF_VT1 : OFF_VT0);

        #pragma unroll
        for (int hf = 0; hf < 2; hf++) {
            bool keep[4];
            #pragma unroll
            for (int p = 0; p < 4; p++)
                keep[p] = (kt * 128 + 64 * hf + 16 * p) <= rmaxg;
            if (!keep[0]) continue;

            float sc[8][4];
            #pragma unroll
            for (int nf = 0; nf < 8; nf++)
                #pragma unroll
                for (int j = 0; j < 4; j++) sc[nf][j] = 0.f;

            #pragma unroll
            for (int ks = 0; ks < 4; ks++) {
                uint32_t kb[4][4];
                #pragma unroll
                for (int p = 0; p < 4; p++)
                    if (keep[p])
                        ldsm4(kb[p], Kb + (64 * hf + 16 * p + krow) * AKSTR + ks * 32 + kbyte);
                #pragma unroll
                for (int p = 0; p < 4; p++) {
                    if (!keep[p]) continue;
                    mma_f16(sc[2 * p],     qa[ks], &kb[p][0]);
                    mma_f16(sc[2 * p + 1], qa[ks], &kb[p][2]);
                }
            }

            #pragma unroll
            for (int nf = 0; nf < 8; nf++) {
                int c0 = kt * 128 + 64 * hf + 8 * nf + 2 * t;
                if (c0     > row0g)     sc[nf][0] = -1e30f;
                if (c0 + 1 > row0g)     sc[nf][1] = -1e30f;
                if (c0     > row0g + 8) sc[nf][2] = -1e30f;
                if (c0 + 1 > row0g + 8) sc[nf][3] = -1e30f;
            }

            #pragma unroll
            for (int kk = 0; kk < 4; kk++) {
                if (!keep[kk]) continue;
                uint32_t pa[4];
                pa[0] = h2ex2(packh2(sc[2*kk][0],     sc[2*kk][1]));
                pa[1] = h2ex2(packh2(sc[2*kk][2],     sc[2*kk][3]));
                pa[2] = h2ex2(packh2(sc[2*kk + 1][0], sc[2*kk + 1][1]));
                pa[3] = h2ex2(packh2(sc[2*kk + 1][2], sc[2*kk + 1][3]));
                {
                    float2 f0 = __half22float2(__hadd2(u2h2(pa[0]), u2h2(pa[2])));
                    float2 f1 = __half22float2(__hadd2(u2h2(pa[1]), u2h2(pa[3])));
                    l0 += f0.x + f0.y;
                    l1 += f1.x + f1.y;
                }
                #pragma unroll
                for (int p = 0; p < 4; p++) {
                    uint32_t vb[4];
                    ldsm4(vb, Vb + (16 * p + krow) * AVSTR + 128 * hf + 32 * kk + kbyte);
                    mma_f16(co[2 * p],     pa, &vb[0]);
                    mma_f16(co[2 * p + 1], pa, &vb[2]);
                }
            }
        }
    }

    // cross-lane row-sum reduction (was inside the l-MMA), normalize, store
    l0 += __shfl_xor_sync(0xffffffffu, l0, 1);
    l0 += __shfl_xor_sync(0xffffffffu, l0, 2);
    l1 += __shfl_xor_sync(0xffffffffu, l1, 1);
    l1 += __shfl_xor_sync(0xffffffffu, l1, 2);
    float inv0 = 1.f / l0, inv1 = 1.f / l1;
    float* op0 = out + ((size_t)b * Sn + row0g) * Cn + h * 64;
    float* op1 = op0 + 8 * Cn;
    #pragma unroll
    for (int nf = 0; nf < 8; nf++) {
        int d = 8 * nf + 2 * t;
        *(float2*)(op0 + d) = make_float2(co[nf][0] * inv0, co[nf][1] * inv0);
        *(float2*)(op1 + d) = make_float2(co[nf][2] * inv1, co[nf][3] * inv1);
    }
}

// ---------------------------------------------------------------------------
// Persistent fused kernel: gemm (head-pair-major, flags) then attention.
// Attention order: first 128 items hp-major (hp 0,1 — overlap GEMM tail),
// remaining 384 items LPT (qt descending across hp 2..7) to balance the tail.
// ---------------------------------------------------------------------------
__global__ __launch_bounds__(256, 2) void gemm_attn_kernel(const float* __restrict__ bqk,
                                                           const float* __restrict__ bv,
                                                           float* __restrict__ out) {
    extern __shared__ __align__(128) char smem[];
    __shared__ int s_item;
    const int tid = threadIdx.x;

    // ---- phase 1: GEMM (head-pair-major item order) ----
    for (;;) {
        if (tid == 0) s_item = atomicAdd(&g_qgemm, 1);
        __syncthreads();
        int it = s_item;
        __syncthreads();
        if (it >= NGEMM) break;
        int grp = it / 96;                    // head-pair group 0..7
        int w   = it % 96;
        int bn_idx = grp + 8 * (w % 3);       // {grp, grp+8, grp+16}
        int bm_idx = w / 3;                   // 0..31
        gemm_tile(bn_idx * 128, bm_idx * 128, bqk, bv, smem);
        __threadfence();
        __syncthreads();
        if (tid == 0) atomicAdd(&g_gemm_done[grp], 1);
    }

    // ---- phase 2: attention ----
    for (;;) {
        if (tid == 0) s_item = atomicAdd(&g_qattn, 1);
        __syncthreads();
        int j = s_item;
        __syncthreads();
        if (j >= NATTN) break;
        int hp, qt, sub;
        if (j < 128) {
            hp  = j >> 6;
            int r = j & 63;
            qt  = 15 - (r >> 2);
            sub = r & 3;
        } else {
            int idx = j - 128;                // 0..383
            qt  = 15 - idx / 24;
            int r = idx % 24;
            hp  = 2 + (r >> 2);
            sub = r & 3;
        }
        int h = 2 * hp + (sub & 1);
        int b = sub >> 1;
        if (tid == 0) {
            while (atomicAdd(&g_gemm_done[hp], 0) < 96) __nanosleep(128);
        }
        __syncthreads();
        __threadfence();
        attn_item(qt, b, h, out, smem);
    }

    // ---- finish: last CTA resets all counters for the next graph replay ----
    __syncthreads();
    if (tid == 0) {
        int d = atomicAdd(&g_done, 1);
        if (d == NCTA - 1) {
            g_qgemm = 0; g_qattn = 0; g_done = 0;
            #pragma unroll
            for (int i = 0; i < 8; i++) g_gemm_done[i] = 0;
            __threadfence();
        }
    }
}

// ---------------------------------------------------------------------------
extern "C" void kernel_launch(void* const* d_in, const int* in_sizes, int n_in,
                              void* d_out, int out_size) {
    const float* x   = (const float*)d_in[0];
    const float* Wqk = (const float*)d_in[1];
    const float* bqk = (const float*)d_in[2];
    const float* Wv  = (const float*)d_in[3];
    const float* bv  = (const float*)d_in[4];
    float* out = (float*)d_out;

    prep_kernel<<<PREP_XBLK + 3072, 256>>>(x, Wqk, Wv);

    cudaFuncSetAttribute(gemm_attn_kernel, cudaFuncAttributeMaxDynamicSharedMemorySize, FUSED_SMEM);
    gemm_attn_kernel<<<NCTA, 256, FUSED_SMEM>>>(bqk, bv, out);
}